// round 1
// baseline (speedup 1.0000x reference)
#include <cuda_runtime.h>
#include <math.h>

// Problem constants
#define B_ 8
#define S_ 512
#define D_ 512
#define H_ 8
#define DK_ 64
#define DV_ 64
#define DFF_ 2048
#define L_ 6
#define M_ (B_ * S_)               // 4096 rows
#define X_ELEMS (M_ * D_)          // 2,097,152
#define ATTN_PER_LAYER ((long)B_ * H_ * S_ * S_)  // 16,777,216

// Device scratch (allocations are forbidden; use __device__ globals)
__device__ float g_x[X_ELEMS];
__device__ float g_q[X_ELEMS];
__device__ float g_k[X_ELEMS];
__device__ float g_v[X_ELEMS];
__device__ float g_ctx[X_ELEMS];
__device__ float g_tmp[X_ELEMS];
__device__ float g_h1[M_ * DFF_];
__device__ float g_pos[S_ * D_];

// ---------------------------------------------------------------------------
// Positional table: t[s][d] = s / 10000^(2d/D); row 0 = 0; rows>=1: sin even
// cols, cos odd cols. Computed in double to match numpy float64 path.
// ---------------------------------------------------------------------------
__global__ void pos_kernel(float* __restrict__ pos) {
    int idx = blockIdx.x * blockDim.x + threadIdx.x;
    if (idx >= S_ * D_) return;
    int s = idx >> 9;      // / 512
    int d = idx & 511;
    double val = 0.0;
    if (s > 0) {
        double ang = (double)s * exp(-log(10000.0) * (2.0 * (double)d / (double)D_));
        val = (d & 1) ? cos(ang) : sin(ang);
    }
    pos[idx] = (float)val;
}

__global__ void add_pos_kernel(float* __restrict__ x,
                               const float* __restrict__ enc,
                               const float* __restrict__ pos) {
    int idx = blockIdx.x * blockDim.x + threadIdx.x;
    if (idx >= X_ELEMS) return;
    int sd = idx & (S_ * D_ - 1);  // S_*D_ = 262144, power of 2
    x[idx] = enc[idx] + pos[sd];
}

// ---------------------------------------------------------------------------
// Generic batched strided GEMM.
//   C[m,n] = alpha * sum_k A[m,k] * (TB ? B[n,k] : B[k,n])   (+ epilogue)
// Batch index z decomposed as (zb, zh) = (z / hdiv, z % hdiv) with separate
// strides, to address [B,S,H,D*] layouts without relayout passes.
// epi: 0 = none, 1 = relu, 2 = += R[m*ldc+n]
// ---------------------------------------------------------------------------
template <int BM, int BN, int BK, int TM, int TN, bool TB>
__global__ void __launch_bounds__((BM / TM) * (BN / TN))
gemm_k(const float* __restrict__ A, int lda, long sAb, long sAh,
       const float* __restrict__ Bm, int ldb, long sBb, long sBh,
       float* __restrict__ C, int ldc, long sCb, long sCh,
       const float* __restrict__ R,
       int K, float alpha, int epi, int hdiv) {
    constexpr int TH = (BM / TM) * (BN / TN);
    const int z = blockIdx.z;
    const int zb = z / hdiv;
    const int zh = z % hdiv;
    A += (long)zb * sAb + (long)zh * sAh;
    Bm += (long)zb * sBb + (long)zh * sBh;
    C += (long)zb * sCb + (long)zh * sCh;

    __shared__ float As[BK][BM + 1];
    __shared__ __align__(16) float Bs[BK][BN];

    const int tid = threadIdx.x;
    const int m0 = blockIdx.y * BM;
    const int n0 = blockIdx.x * BN;
    const int tc = tid % (BN / TN);
    const int tr = tid / (BN / TN);

    float acc[TM][TN];
#pragma unroll
    for (int i = 0; i < TM; i++)
#pragma unroll
        for (int j = 0; j < TN; j++) acc[i][j] = 0.0f;

    for (int k0 = 0; k0 < K; k0 += BK) {
        // Load A tile (BM x BK), store transposed into As[k][m]
#pragma unroll
        for (int it = 0; it < (BM * BK) / TH; it++) {
            int i = tid + it * TH;
            int am = i / BK;
            int ak = i % BK;
            As[ak][am] = A[(long)(m0 + am) * lda + (k0 + ak)];
        }
        // Load B tile
        if (!TB) {
#pragma unroll
            for (int it = 0; it < (BK * BN) / TH; it++) {
                int i = tid + it * TH;
                int bk = i / BN;
                int bn = i % BN;
                Bs[bk][bn] = Bm[(long)(k0 + bk) * ldb + (n0 + bn)];
            }
        } else {
#pragma unroll
            for (int it = 0; it < (BK * BN) / TH; it++) {
                int i = tid + it * TH;
                int bn = i / BK;
                int bk = i % BK;
                Bs[bk][bn] = Bm[(long)(n0 + bn) * ldb + (k0 + bk)];
            }
        }
        __syncthreads();

#pragma unroll
        for (int kk = 0; kk < BK; kk++) {
            float ra[TM];
#pragma unroll
            for (int i = 0; i < TM; i++) ra[i] = As[kk][tr * TM + i];
            float rb[TN];
            const float4* b4 = reinterpret_cast<const float4*>(&Bs[kk][tc * TN]);
#pragma unroll
            for (int j = 0; j < TN / 4; j++) {
                float4 t4 = b4[j];
                rb[4 * j + 0] = t4.x;
                rb[4 * j + 1] = t4.y;
                rb[4 * j + 2] = t4.z;
                rb[4 * j + 3] = t4.w;
            }
#pragma unroll
            for (int i = 0; i < TM; i++)
#pragma unroll
                for (int j = 0; j < TN; j++) acc[i][j] = fmaf(ra[i], rb[j], acc[i][j]);
        }
        __syncthreads();
    }

#pragma unroll
    for (int i = 0; i < TM; i++) {
        int m = m0 + tr * TM + i;
#pragma unroll
        for (int j = 0; j < TN; j++) {
            int n = n0 + tc * TN + j;
            float vv = acc[i][j] * alpha;
            if (epi == 1) vv = fmaxf(vv, 0.0f);
            else if (epi == 2) vv += R[(long)m * ldc + n];
            C[(long)m * ldc + n] = vv;
        }
    }
}

// ---------------------------------------------------------------------------
// In-place row softmax over the attn region. Row layout [b,h,q] x 512 keys.
// Pad keys (mask==0) behave as logit=-1e9 -> prob 0 (matches ref underflow).
// ---------------------------------------------------------------------------
__global__ void softmax_kernel(float* __restrict__ attn, const int* __restrict__ mask) {
    const int row = blockIdx.x;           // b*H*S + h*S + q
    const int b = row >> 12;              // / (H_*S_) = 4096
    float* p = attn + (long)row * S_;
    const int* mrow = mask + b * S_;
    const int t = threadIdx.x;

    float v0 = (mrow[t] == 0) ? -1e9f : p[t];
    float v1 = (mrow[t + 256] == 0) ? -1e9f : p[t + 256];

    __shared__ float red[256];
    red[t] = fmaxf(v0, v1);
    __syncthreads();
#pragma unroll
    for (int s = 128; s > 0; s >>= 1) {
        if (t < s) red[t] = fmaxf(red[t], red[t + s]);
        __syncthreads();
    }
    const float m = red[0];
    __syncthreads();

    float e0 = expf(v0 - m);
    float e1 = expf(v1 - m);
    red[t] = e0 + e1;
    __syncthreads();
#pragma unroll
    for (int s = 128; s > 0; s >>= 1) {
        if (t < s) red[t] += red[t + s];
        __syncthreads();
    }
    const float inv = 1.0f / red[0];
    p[t] = e0 * inv;
    p[t + 256] = e1 * inv;
}

// ---------------------------------------------------------------------------
// LayerNorm over last dim (512). Two-pass (mean, then E[(x-m)^2]) to match ref.
// ---------------------------------------------------------------------------
__global__ void ln_kernel(const float* __restrict__ in,
                          const float* __restrict__ g,
                          const float* __restrict__ bb,
                          float* __restrict__ out) {
    const int row = blockIdx.x;
    const float* p = in + (long)row * D_;
    const int t = threadIdx.x;

    float x0 = p[t];
    float x1 = p[t + 256];

    __shared__ float red[256];
    red[t] = x0 + x1;
    __syncthreads();
#pragma unroll
    for (int s = 128; s > 0; s >>= 1) {
        if (t < s) red[t] += red[t + s];
        __syncthreads();
    }
    const float mean = red[0] * (1.0f / D_);
    __syncthreads();

    float d0 = x0 - mean;
    float d1 = x1 - mean;
    red[t] = d0 * d0 + d1 * d1;
    __syncthreads();
#pragma unroll
    for (int s = 128; s > 0; s >>= 1) {
        if (t < s) red[t] += red[t + s];
        __syncthreads();
    }
    const float var = red[0] * (1.0f / D_);
    const float rs = rsqrtf(var + 1e-5f);

    float* o = out + (long)row * D_;
    o[t] = d0 * rs * g[t] + bb[t];
    o[t + 256] = d1 * rs * g[t + 256] + bb[t + 256];
}

// ---------------------------------------------------------------------------
// Launch: full 6-layer encoder.
// Inputs: 0 enc_inputs, 1 mask, 2 Wq, 3 Wk, 4 Wv, 5 Wo, 6 ln1_g, 7 ln1_b,
//         8 W1, 9 W2, 10 ln2_g, 11 ln2_b
// Output: [x (2,097,152 f32)] [attns (6 x 16,777,216 f32)]
// ---------------------------------------------------------------------------
extern "C" void kernel_launch(void* const* d_in, const int* in_sizes, int n_in,
                              void* d_out, int out_size) {
    const float* enc = (const float*)d_in[0];
    const int* mask = (const int*)d_in[1];
    const float* Wq = (const float*)d_in[2];
    const float* Wk = (const float*)d_in[3];
    const float* Wv = (const float*)d_in[4];
    const float* Wo = (const float*)d_in[5];
    const float* ln1g = (const float*)d_in[6];
    const float* ln1b = (const float*)d_in[7];
    const float* W1 = (const float*)d_in[8];
    const float* W2 = (const float*)d_in[9];
    const float* ln2g = (const float*)d_in[10];
    const float* ln2b = (const float*)d_in[11];

    float *x, *q, *k, *v, *ctx, *tmp, *h1, *pos;
    cudaGetSymbolAddress((void**)&x, g_x);
    cudaGetSymbolAddress((void**)&q, g_q);
    cudaGetSymbolAddress((void**)&k, g_k);
    cudaGetSymbolAddress((void**)&v, g_v);
    cudaGetSymbolAddress((void**)&ctx, g_ctx);
    cudaGetSymbolAddress((void**)&tmp, g_tmp);
    cudaGetSymbolAddress((void**)&h1, g_h1);
    cudaGetSymbolAddress((void**)&pos, g_pos);

    float* out_x = (float*)d_out;
    float* out_attn = out_x + X_ELEMS;

    pos_kernel<<<(S_ * D_ + 255) / 256, 256>>>(pos);
    add_pos_kernel<<<(X_ELEMS + 255) / 256, 256>>>(x, enc, pos);

    const long WLD = (long)D_ * D_;       // 262144 per-layer weight stride (D x D)
    const long WF = (long)D_ * DFF_;      // 1048576 per-layer FFN weight stride

    for (int l = 0; l < L_; l++) {
        const float* Wq_l = Wq + l * WLD;
        const float* Wk_l = Wk + l * WLD;
        const float* Wv_l = Wv + l * WLD;
        const float* Wo_l = Wo + l * WLD;
        const float* W1_l = W1 + l * WF;
        const float* W2_l = W2 + l * WF;
        float* attn_l = out_attn + (long)l * ATTN_PER_LAYER;

        // Q, K, V projections: [4096,512] @ [512,512]
        gemm_k<128, 128, 16, 8, 8, false><<<dim3(4, 32, 1), 256>>>(
            x, D_, 0, 0, Wq_l, D_, 0, 0, q, D_, 0, 0, nullptr, D_, 1.0f, 0, 1);
        gemm_k<128, 128, 16, 8, 8, false><<<dim3(4, 32, 1), 256>>>(
            x, D_, 0, 0, Wk_l, D_, 0, 0, k, D_, 0, 0, nullptr, D_, 1.0f, 0, 1);
        gemm_k<128, 128, 16, 8, 8, false><<<dim3(4, 32, 1), 256>>>(
            x, D_, 0, 0, Wv_l, D_, 0, 0, v, D_, 0, 0, nullptr, D_, 1.0f, 0, 1);

        // Scores: per (b,h): Q[512,64] @ K^T -> attn region, scaled by 1/8
        gemm_k<128, 128, 16, 8, 8, true><<<dim3(4, 4, B_ * H_), 256>>>(
            q, D_, (long)S_ * D_, DK_,
            k, D_, (long)S_ * D_, DK_,
            attn_l, S_, (long)H_ * S_ * S_, (long)S_ * S_,
            nullptr, DK_, 0.125f, 0, H_);

        // Softmax (in place, applies pad mask)
        softmax_kernel<<<B_ * H_ * S_, 256>>>(attn_l, mask);

        // ctx: per (b,h): attn[512,512] @ V[512,64] -> [B,S,H,DV] layout
        gemm_k<64, 64, 16, 4, 4, false><<<dim3(1, 8, B_ * H_), 256>>>(
            attn_l, S_, (long)H_ * S_ * S_, (long)S_ * S_,
            v, D_, (long)S_ * D_, DV_,
            ctx, D_, (long)S_ * D_, DV_,
            nullptr, S_, 1.0f, 0, H_);

        // Wo projection + residual
        gemm_k<128, 128, 16, 8, 8, false><<<dim3(4, 32, 1), 256>>>(
            ctx, D_, 0, 0, Wo_l, D_, 0, 0, tmp, D_, 0, 0, x, D_, 1.0f, 2, 1);
        ln_kernel<<<M_, 256>>>(tmp, ln1g + l * D_, ln1b + l * D_, x);

        // FFN: relu(x @ W1) @ W2 + x
        gemm_k<128, 128, 16, 8, 8, false><<<dim3(16, 32, 1), 256>>>(
            x, D_, 0, 0, W1_l, DFF_, 0, 0, h1, DFF_, 0, 0, nullptr, D_, 1.0f, 1, 1);
        gemm_k<128, 128, 16, 8, 8, false><<<dim3(4, 32, 1), 256>>>(
            h1, DFF_, 0, 0, W2_l, D_, 0, 0, tmp, D_, 0, 0, x, DFF_, 1.0f, 2, 1);
        ln_kernel<<<M_, 256>>>(tmp, ln2g + l * D_, ln2b + l * D_, x);
    }

    cudaMemcpyAsync(out_x, x, (size_t)X_ELEMS * sizeof(float),
                    cudaMemcpyDeviceToDevice, 0);
}

// round 2
// speedup vs baseline: 2.6693x; 2.6693x over previous
#include <cuda_runtime.h>
#include <math.h>

// Problem constants
#define B_ 8
#define S_ 512
#define D_ 512
#define H_ 8
#define DK_ 64
#define DV_ 64
#define DFF_ 2048
#define L_ 6
#define M_ (B_ * S_)               // 4096 rows
#define X_ELEMS (M_ * D_)          // 2,097,152
#define ATTN_PER_LAYER ((long)B_ * H_ * S_ * S_)  // 16,777,216

// Device scratch (allocations are forbidden; use __device__ globals)
__device__ float g_x[X_ELEMS];
__device__ float g_q[X_ELEMS];
__device__ float g_k[X_ELEMS];
__device__ float g_v[X_ELEMS];
__device__ float g_ctx[X_ELEMS];
__device__ float g_tmp[X_ELEMS];
__device__ float g_h1[M_ * DFF_];
__device__ float g_pos[S_ * D_];

// ---------------------------------------------------------------------------
// tf32 helpers
// ---------------------------------------------------------------------------
__device__ __forceinline__ unsigned f2tf(float x) {
    unsigned r;
    asm("cvt.rna.tf32.f32 %0, %1;" : "=r"(r) : "f"(x));
    return r;
}

__device__ __forceinline__ void mma8(float* d, const unsigned* a, const unsigned* b) {
    asm volatile(
        "mma.sync.aligned.m16n8k8.row.col.f32.tf32.tf32.f32 "
        "{%0,%1,%2,%3}, {%4,%5,%6,%7}, {%8,%9}, {%0,%1,%2,%3};"
        : "+f"(d[0]), "+f"(d[1]), "+f"(d[2]), "+f"(d[3])
        : "r"(a[0]), "r"(a[1]), "r"(a[2]), "r"(a[3]), "r"(b[0]), "r"(b[1]));
}

// ---------------------------------------------------------------------------
// Positional table (double precision to match numpy float64 path)
// ---------------------------------------------------------------------------
__global__ void pos_kernel(float* __restrict__ pos) {
    int idx = blockIdx.x * blockDim.x + threadIdx.x;
    if (idx >= S_ * D_) return;
    int s = idx >> 9;
    int d = idx & 511;
    double val = 0.0;
    if (s > 0) {
        double ang = (double)s * exp(-log(10000.0) * (2.0 * (double)d / (double)D_));
        val = (d & 1) ? cos(ang) : sin(ang);
    }
    pos[idx] = (float)val;
}

__global__ void add_pos_kernel(float* __restrict__ x,
                               const float* __restrict__ enc,
                               const float* __restrict__ pos) {
    int idx = blockIdx.x * blockDim.x + threadIdx.x;
    if (idx >= X_ELEMS) return;
    int sd = idx & (S_ * D_ - 1);
    x[idx] = enc[idx] + pos[sd];
}

// ---------------------------------------------------------------------------
// TF32 tensor-core GEMM body.
//   C[m,n] = alpha * sum_k A[m,k] * (TB ? B[n,k] : B[k,n])  (+ epilogue)
// Block: 256 threads (8 warps, 2 rows x 4 cols). Warp tile: (BM/2) x (BN/4).
// Tiles: BM x BN x 16, double-buffered, register-staged global prefetch.
// epi: 0 = none, 1 = relu, 2 = += R[m*ldc+n]
// All dims assumed divisible (BM | M, BN | N, 16 | K) — true for this problem.
// ---------------------------------------------------------------------------
template <int BM, int BN, bool TB>
__device__ __forceinline__ void gemm_body(
    float* __restrict__ As, float* __restrict__ Bs,
    const float* __restrict__ A, int lda,
    const float* __restrict__ Bg, int ldb,
    float* __restrict__ C, int ldc,
    const float* __restrict__ R,
    int K, float alpha, int epi) {
    constexpr int ASTR = 20;          // A smem row stride (pad 4) — conflict-free frags
    constexpr int BSTR = BN + 8;      // B smem row stride (pad 8) — conflict-free frags
    constexpr int ABUF = BM * ASTR;
    constexpr int BBUF = 16 * BSTR;
    constexpr int AF = (BM * 4) / 256;    // float4 A loads per thread per chunk
    constexpr int BF = (BN * 4) / 256;    // float4 B loads per thread per chunk
    constexpr int WM = BM / 2, WN = BN / 4;
    constexpr int MT = WM / 16, NT = WN / 8;

    const int tid = threadIdx.x;
    const int lane = tid & 31;
    const int warp = tid >> 5;
    const int g = lane >> 2;      // groupID
    const int tg = lane & 3;      // threadID_in_group
    const int wr = warp & 1;
    const int wc = warp >> 1;
    const int m0 = blockIdx.y * BM;
    const int n0 = blockIdx.x * BN;

    float4 ra[AF], rb[BF];

    auto gload = [&](int k0) {
#pragma unroll
        for (int it = 0; it < AF; it++) {
            int f = tid + it * 256;
            ra[it] = *reinterpret_cast<const float4*>(
                &A[(long)(m0 + (f >> 2)) * lda + k0 + (f & 3) * 4]);
        }
#pragma unroll
        for (int it = 0; it < BF; it++) {
            int f = tid + it * 256;
            if (!TB) {
                int row = f / (BN / 4), c4 = f % (BN / 4);
                rb[it] = *reinterpret_cast<const float4*>(
                    &Bg[(long)(k0 + row) * ldb + n0 + c4 * 4]);
            } else {
                int n = f >> 2, k4 = f & 3;
                rb[it] = *reinterpret_cast<const float4*>(
                    &Bg[(long)(n0 + n) * ldb + k0 + k4 * 4]);
            }
        }
    };

    auto sstore = [&](int buf) {
        float* ab = As + buf * ABUF;
        float* bb = Bs + buf * BBUF;
#pragma unroll
        for (int it = 0; it < AF; it++) {
            int f = tid + it * 256;
            float4 w;
            w.x = __uint_as_float(f2tf(ra[it].x));
            w.y = __uint_as_float(f2tf(ra[it].y));
            w.z = __uint_as_float(f2tf(ra[it].z));
            w.w = __uint_as_float(f2tf(ra[it].w));
            *reinterpret_cast<float4*>(&ab[(f >> 2) * ASTR + (f & 3) * 4]) = w;
        }
#pragma unroll
        for (int it = 0; it < BF; it++) {
            int f = tid + it * 256;
            if (!TB) {
                int row = f / (BN / 4), c4 = f % (BN / 4);
                float4 w;
                w.x = __uint_as_float(f2tf(rb[it].x));
                w.y = __uint_as_float(f2tf(rb[it].y));
                w.z = __uint_as_float(f2tf(rb[it].z));
                w.w = __uint_as_float(f2tf(rb[it].w));
                *reinterpret_cast<float4*>(&bb[row * BSTR + c4 * 4]) = w;
            } else {
                int n = f >> 2, k4 = f & 3;
                bb[(k4 * 4 + 0) * BSTR + n] = __uint_as_float(f2tf(rb[it].x));
                bb[(k4 * 4 + 1) * BSTR + n] = __uint_as_float(f2tf(rb[it].y));
                bb[(k4 * 4 + 2) * BSTR + n] = __uint_as_float(f2tf(rb[it].z));
                bb[(k4 * 4 + 3) * BSTR + n] = __uint_as_float(f2tf(rb[it].w));
            }
        }
    };

    float acc[MT][NT][4];
#pragma unroll
    for (int i = 0; i < MT; i++)
#pragma unroll
        for (int j = 0; j < NT; j++)
#pragma unroll
            for (int e = 0; e < 4; e++) acc[i][j][e] = 0.0f;

    gload(0);
    sstore(0);
    __syncthreads();

    const int nchunks = K / 16;
    for (int c = 0; c < nchunks; c++) {
        const int buf = c & 1;
        if (c + 1 < nchunks) gload((c + 1) * 16);

        const float* ab = As + buf * ABUF;
        const float* bb = Bs + buf * BBUF;
#pragma unroll
        for (int ks = 0; ks < 2; ks++) {
            unsigned afr[MT][4], bfr[NT][2];
#pragma unroll
            for (int i = 0; i < MT; i++) {
                int r = wr * WM + i * 16;
                afr[i][0] = __float_as_uint(ab[(r + g) * ASTR + ks * 8 + tg]);
                afr[i][1] = __float_as_uint(ab[(r + 8 + g) * ASTR + ks * 8 + tg]);
                afr[i][2] = __float_as_uint(ab[(r + g) * ASTR + ks * 8 + 4 + tg]);
                afr[i][3] = __float_as_uint(ab[(r + 8 + g) * ASTR + ks * 8 + 4 + tg]);
            }
#pragma unroll
            for (int j = 0; j < NT; j++) {
                int n = wc * WN + j * 8 + g;
                bfr[j][0] = __float_as_uint(bb[(ks * 8 + tg) * BSTR + n]);
                bfr[j][1] = __float_as_uint(bb[(ks * 8 + 4 + tg) * BSTR + n]);
            }
#pragma unroll
            for (int i = 0; i < MT; i++)
#pragma unroll
                for (int j = 0; j < NT; j++) mma8(acc[i][j], afr[i], bfr[j]);
        }

        if (c + 1 < nchunks) sstore(buf ^ 1);
        __syncthreads();
    }

    // Epilogue
#pragma unroll
    for (int i = 0; i < MT; i++) {
        int r0 = m0 + wr * WM + i * 16 + g;
#pragma unroll
        for (int j = 0; j < NT; j++) {
            int col = n0 + wc * WN + j * 8 + tg * 2;
            float v0 = acc[i][j][0] * alpha;
            float v1 = acc[i][j][1] * alpha;
            float v2 = acc[i][j][2] * alpha;
            float v3 = acc[i][j][3] * alpha;
            if (epi == 1) {
                v0 = fmaxf(v0, 0.0f); v1 = fmaxf(v1, 0.0f);
                v2 = fmaxf(v2, 0.0f); v3 = fmaxf(v3, 0.0f);
            } else if (epi == 2) {
                v0 += R[(long)r0 * ldc + col];
                v1 += R[(long)r0 * ldc + col + 1];
                v2 += R[(long)(r0 + 8) * ldc + col];
                v3 += R[(long)(r0 + 8) * ldc + col + 1];
            }
            float2 p01; p01.x = v0; p01.y = v1;
            float2 p23; p23.x = v2; p23.y = v3;
            *reinterpret_cast<float2*>(&C[(long)r0 * ldc + col]) = p01;
            *reinterpret_cast<float2*>(&C[(long)(r0 + 8) * ldc + col]) = p23;
        }
    }
}

template <int BM, int BN, bool TB>
__global__ void __launch_bounds__(256, 2)
gemm_mma(const float* __restrict__ A, int lda, long sAb, long sAh,
         const float* __restrict__ Bg, int ldb, long sBb, long sBh,
         float* __restrict__ C, int ldc, long sCb, long sCh,
         const float* __restrict__ R,
         int K, float alpha, int epi, int hdiv) {
    __shared__ float As[2 * BM * 20];
    __shared__ float Bs[2 * 16 * (BN + 8)];
    const int z = blockIdx.z;
    const int zb = z / hdiv;
    const int zh = z % hdiv;
    gemm_body<BM, BN, TB>(As, Bs,
                          A + (long)zb * sAb + (long)zh * sAh, lda,
                          Bg + (long)zb * sBb + (long)zh * sBh, ldb,
                          C + (long)zb * sCb + (long)zh * sCh, ldc,
                          R, K, alpha, epi);
}

// Fused Q/K/V projection: blockIdx.z selects the weight/output pair.
__global__ void __launch_bounds__(256, 2)
qkv_mma(const float* __restrict__ x,
        const float* __restrict__ Wq, const float* __restrict__ Wk,
        const float* __restrict__ Wv,
        float* __restrict__ q, float* __restrict__ k, float* __restrict__ v) {
    __shared__ float As[2 * 128 * 20];
    __shared__ float Bs[2 * 16 * 136];
    const int z = blockIdx.z;
    const float* W = (z == 0) ? Wq : (z == 1) ? Wk : Wv;
    float* C = (z == 0) ? q : (z == 1) ? k : v;
    gemm_body<128, 128, false>(As, Bs, x, D_, W, D_, C, D_, nullptr, D_, 1.0f, 0);
}

// ---------------------------------------------------------------------------
// In-place row softmax; pad keys (mask==0) -> logit -1e9 -> prob ~0.
// ---------------------------------------------------------------------------
__global__ void softmax_kernel(float* __restrict__ attn, const int* __restrict__ mask) {
    const int row = blockIdx.x;
    const int b = row >> 12;
    float* p = attn + (long)row * S_;
    const int* mrow = mask + b * S_;
    const int t = threadIdx.x;

    float v0 = (mrow[t] == 0) ? -1e9f : p[t];
    float v1 = (mrow[t + 256] == 0) ? -1e9f : p[t + 256];

    __shared__ float red[256];
    red[t] = fmaxf(v0, v1);
    __syncthreads();
#pragma unroll
    for (int s = 128; s > 0; s >>= 1) {
        if (t < s) red[t] = fmaxf(red[t], red[t + s]);
        __syncthreads();
    }
    const float m = red[0];
    __syncthreads();

    float e0 = expf(v0 - m);
    float e1 = expf(v1 - m);
    red[t] = e0 + e1;
    __syncthreads();
#pragma unroll
    for (int s = 128; s > 0; s >>= 1) {
        if (t < s) red[t] += red[t + s];
        __syncthreads();
    }
    const float inv = 1.0f / red[0];
    p[t] = e0 * inv;
    p[t + 256] = e1 * inv;
}

// ---------------------------------------------------------------------------
// LayerNorm over last dim (512)
// ---------------------------------------------------------------------------
__global__ void ln_kernel(const float* __restrict__ in,
                          const float* __restrict__ g,
                          const float* __restrict__ bb,
                          float* __restrict__ out) {
    const int row = blockIdx.x;
    const float* p = in + (long)row * D_;
    const int t = threadIdx.x;

    float x0 = p[t];
    float x1 = p[t + 256];

    __shared__ float red[256];
    red[t] = x0 + x1;
    __syncthreads();
#pragma unroll
    for (int s = 128; s > 0; s >>= 1) {
        if (t < s) red[t] += red[t + s];
        __syncthreads();
    }
    const float mean = red[0] * (1.0f / D_);
    __syncthreads();

    float d0 = x0 - mean;
    float d1 = x1 - mean;
    red[t] = d0 * d0 + d1 * d1;
    __syncthreads();
#pragma unroll
    for (int s = 128; s > 0; s >>= 1) {
        if (t < s) red[t] += red[t + s];
        __syncthreads();
    }
    const float var = red[0] * (1.0f / D_);
    const float rs = rsqrtf(var + 1e-5f);

    float* o = out + (long)row * D_;
    o[t] = d0 * rs * g[t] + bb[t];
    o[t + 256] = d1 * rs * g[t + 256] + bb[t + 256];
}

// ---------------------------------------------------------------------------
extern "C" void kernel_launch(void* const* d_in, const int* in_sizes, int n_in,
                              void* d_out, int out_size) {
    const float* enc = (const float*)d_in[0];
    const int* mask = (const int*)d_in[1];
    const float* Wq = (const float*)d_in[2];
    const float* Wk = (const float*)d_in[3];
    const float* Wv = (const float*)d_in[4];
    const float* Wo = (const float*)d_in[5];
    const float* ln1g = (const float*)d_in[6];
    const float* ln1b = (const float*)d_in[7];
    const float* W1 = (const float*)d_in[8];
    const float* W2 = (const float*)d_in[9];
    const float* ln2g = (const float*)d_in[10];
    const float* ln2b = (const float*)d_in[11];

    float *x, *q, *k, *v, *ctx, *tmp, *h1, *pos;
    cudaGetSymbolAddress((void**)&x, g_x);
    cudaGetSymbolAddress((void**)&q, g_q);
    cudaGetSymbolAddress((void**)&k, g_k);
    cudaGetSymbolAddress((void**)&v, g_v);
    cudaGetSymbolAddress((void**)&ctx, g_ctx);
    cudaGetSymbolAddress((void**)&tmp, g_tmp);
    cudaGetSymbolAddress((void**)&h1, g_h1);
    cudaGetSymbolAddress((void**)&pos, g_pos);

    float* out_x = (float*)d_out;
    float* out_attn = out_x + X_ELEMS;

    pos_kernel<<<(S_ * D_ + 255) / 256, 256>>>(pos);
    add_pos_kernel<<<(X_ELEMS + 255) / 256, 256>>>(x, enc, pos);

    const long WLD = (long)D_ * D_;
    const long WF = (long)D_ * DFF_;

    for (int l = 0; l < L_; l++) {
        const float* Wo_l = Wo + l * WLD;
        const float* W1_l = W1 + l * WF;
        const float* W2_l = W2 + l * WF;
        float* attn_l = out_attn + (long)l * ATTN_PER_LAYER;

        // Fused Q,K,V projections: [4096,512] @ [512,512] x3
        qkv_mma<<<dim3(4, 32, 3), 256>>>(x, Wq + l * WLD, Wk + l * WLD, Wv + l * WLD,
                                         q, k, v);

        // Scores: per (b,h): Q[512,64] @ K^T * (1/8) -> attn region
        gemm_mma<128, 128, true><<<dim3(4, 4, B_ * H_), 256>>>(
            q, D_, (long)S_ * D_, DK_,
            k, D_, (long)S_ * D_, DK_,
            attn_l, S_, (long)H_ * S_ * S_, (long)S_ * S_,
            nullptr, DK_, 0.125f, 0, H_);

        // Softmax (in place, applies pad mask)
        softmax_kernel<<<B_ * H_ * S_, 256>>>(attn_l, mask);

        // ctx: per (b,h): attn[512,512] @ V[512,64] -> [B,S,H,DV]
        gemm_mma<128, 64, false><<<dim3(1, 4, B_ * H_), 256>>>(
            attn_l, S_, (long)H_ * S_ * S_, (long)S_ * S_,
            v, D_, (long)S_ * D_, DV_,
            ctx, D_, (long)S_ * D_, DV_,
            nullptr, S_, 1.0f, 0, H_);

        // Wo projection + residual, then LN1
        gemm_mma<128, 128, false><<<dim3(4, 32, 1), 256>>>(
            ctx, D_, 0, 0, Wo_l, D_, 0, 0, tmp, D_, 0, 0, x, D_, 1.0f, 2, 1);
        ln_kernel<<<M_, 256>>>(tmp, ln1g + l * D_, ln1b + l * D_, x);

        // FFN: relu(x @ W1) @ W2 + x, then LN2
        gemm_mma<128, 128, false><<<dim3(16, 32, 1), 256>>>(
            x, D_, 0, 0, W1_l, DFF_, 0, 0, h1, DFF_, 0, 0, nullptr, D_, 1.0f, 1, 1);
        gemm_mma<128, 128, false><<<dim3(4, 32, 1), 256>>>(
            h1, DFF_, 0, 0, W2_l, D_, 0, 0, tmp, D_, 0, 0, x, DFF_, 1.0f, 2, 1);
        ln_kernel<<<M_, 256>>>(tmp, ln2g + l * D_, ln2b + l * D_, x);
    }

    cudaMemcpyAsync(out_x, x, (size_t)X_ELEMS * sizeof(float),
                    cudaMemcpyDeviceToDevice, 0);
}

// round 3
// speedup vs baseline: 3.1192x; 1.1685x over previous
#include <cuda_runtime.h>
#include <math.h>

// Problem constants
#define B_ 8
#define S_ 512
#define D_ 512
#define H_ 8
#define DK_ 64
#define DV_ 64
#define DFF_ 2048
#define L_ 6
#define M_ (B_ * S_)               // 4096 rows
#define X_ELEMS (M_ * D_)          // 2,097,152
#define ATTN_PER_LAYER ((long)B_ * H_ * S_ * S_)  // 16,777,216

// Device scratch (allocations are forbidden; use __device__ globals)
__device__ float g_x[X_ELEMS];
__device__ float g_q[X_ELEMS];
__device__ float g_k[X_ELEMS];
__device__ float g_v[X_ELEMS];
__device__ float g_ctx[X_ELEMS];
__device__ float g_tmp[X_ELEMS];
__device__ float g_h1[M_ * DFF_];
__device__ float g_pos[S_ * D_];

// ---------------------------------------------------------------------------
// tf32 / mma / ldmatrix helpers
// ---------------------------------------------------------------------------
__device__ __forceinline__ unsigned f2tf(float x) {
    unsigned r;
    asm("cvt.rna.tf32.f32 %0, %1;" : "=r"(r) : "f"(x));
    return r;
}

__device__ __forceinline__ void mma8(float* d, const unsigned* a, const unsigned* b) {
    asm volatile(
        "mma.sync.aligned.m16n8k8.row.col.f32.tf32.tf32.f32 "
        "{%0,%1,%2,%3}, {%4,%5,%6,%7}, {%8,%9}, {%0,%1,%2,%3};"
        : "+f"(d[0]), "+f"(d[1]), "+f"(d[2]), "+f"(d[3])
        : "r"(a[0]), "r"(a[1]), "r"(a[2]), "r"(a[3]), "r"(b[0]), "r"(b[1]));
}

__device__ __forceinline__ void ldsm_x4(unsigned* r, unsigned addr) {
    asm volatile("ldmatrix.sync.aligned.m8n8.x4.shared.b16 {%0,%1,%2,%3}, [%4];"
                 : "=r"(r[0]), "=r"(r[1]), "=r"(r[2]), "=r"(r[3]) : "r"(addr));
}

__device__ __forceinline__ void ldsm_x2(unsigned* r, unsigned addr) {
    asm volatile("ldmatrix.sync.aligned.m8n8.x2.shared.b16 {%0,%1}, [%2];"
                 : "=r"(r[0]), "=r"(r[1]) : "r"(addr));
}

// ---------------------------------------------------------------------------
// Positional table (double precision to match numpy float64 path)
// ---------------------------------------------------------------------------
__global__ void pos_kernel(float* __restrict__ pos) {
    int idx = blockIdx.x * blockDim.x + threadIdx.x;
    if (idx >= S_ * D_) return;
    int s = idx >> 9;
    int d = idx & 511;
    double val = 0.0;
    if (s > 0) {
        double ang = (double)s * exp(-log(10000.0) * (2.0 * (double)d / (double)D_));
        val = (d & 1) ? cos(ang) : sin(ang);
    }
    pos[idx] = (float)val;
}

__global__ void add_pos_kernel(float* __restrict__ x,
                               const float* __restrict__ enc,
                               const float* __restrict__ pos) {
    int idx = blockIdx.x * blockDim.x + threadIdx.x;
    if (idx >= X_ELEMS) return;
    int sd = idx & (S_ * D_ - 1);
    x[idx] = enc[idx] + pos[sd];
}

// ---------------------------------------------------------------------------
// TF32 tensor-core GEMM body (ldmatrix fragment loads).
//   C[m,n] = alpha * sum_k A[m,k] * (TB ? B[n,k] : B[k,n])  (+ epilogue)
// Block: 256 threads (8 warps, 2 x 4). Warp tile: (BM/2) x (BN/4).
// A smem: row-major [BM][16], stride 20 (ldmatrix conflict-free).
// B smem: TB -> n-major [BN][16] stride 20 (ldmatrix.x2);
//         !TB -> k-major [16][BN+8] (scalar conflict-free LDS).
// epi: 0 = none, 1 = relu, 2 = += R[m*ldc+n]
// ---------------------------------------------------------------------------
template <int BM, int BN, bool TB>
__device__ __forceinline__ void gemm_body(
    float* __restrict__ As, float* __restrict__ Bs,
    const float* __restrict__ A, int lda,
    const float* __restrict__ Bg, int ldb,
    float* __restrict__ C, int ldc,
    const float* __restrict__ R,
    int K, float alpha, int epi) {
    constexpr int ASTR = 20;
    constexpr int ABUF = BM * ASTR;
    constexpr int BSTR = TB ? 20 : (BN + 8);
    constexpr int BBUF = TB ? (BN * 20) : (16 * BSTR);
    constexpr int AF = (BM * 4) / 256;
    constexpr int BF = (BN * 4) / 256;
    constexpr int WM = BM / 2, WN = BN / 4;
    constexpr int MT = WM / 16, NT = WN / 8;

    const int tid = threadIdx.x;
    const int lane = tid & 31;
    const int warp = tid >> 5;
    const int g = lane >> 2;
    const int tg = lane & 3;
    const int wr = warp & 1;
    const int wc = warp >> 1;
    const int m0 = blockIdx.y * BM;
    const int n0 = blockIdx.x * BN;

    float4 ra[AF], rb[BF];

    auto gload = [&](int k0) {
#pragma unroll
        for (int it = 0; it < AF; it++) {
            int f = tid + it * 256;
            ra[it] = *reinterpret_cast<const float4*>(
                &A[(long)(m0 + (f >> 2)) * lda + k0 + (f & 3) * 4]);
        }
#pragma unroll
        for (int it = 0; it < BF; it++) {
            int f = tid + it * 256;
            if (!TB) {
                int row = f / (BN / 4), c4 = f % (BN / 4);
                rb[it] = *reinterpret_cast<const float4*>(
                    &Bg[(long)(k0 + row) * ldb + n0 + c4 * 4]);
            } else {
                int n = f >> 2, k4 = f & 3;
                rb[it] = *reinterpret_cast<const float4*>(
                    &Bg[(long)(n0 + n) * ldb + k0 + k4 * 4]);
            }
        }
    };

    auto sstore = [&](int buf) {
        float* ab = As + buf * ABUF;
        float* bb = Bs + buf * BBUF;
#pragma unroll
        for (int it = 0; it < AF; it++) {
            int f = tid + it * 256;
            float4 w;
            w.x = __uint_as_float(f2tf(ra[it].x));
            w.y = __uint_as_float(f2tf(ra[it].y));
            w.z = __uint_as_float(f2tf(ra[it].z));
            w.w = __uint_as_float(f2tf(ra[it].w));
            *reinterpret_cast<float4*>(&ab[(f >> 2) * ASTR + (f & 3) * 4]) = w;
        }
#pragma unroll
        for (int it = 0; it < BF; it++) {
            int f = tid + it * 256;
            float4 w;
            w.x = __uint_as_float(f2tf(rb[it].x));
            w.y = __uint_as_float(f2tf(rb[it].y));
            w.z = __uint_as_float(f2tf(rb[it].z));
            w.w = __uint_as_float(f2tf(rb[it].w));
            if (!TB) {
                int row = f / (BN / 4), c4 = f % (BN / 4);
                *reinterpret_cast<float4*>(&bb[row * BSTR + c4 * 4]) = w;
            } else {
                int n = f >> 2, k4 = f & 3;
                *reinterpret_cast<float4*>(&bb[n * 20 + k4 * 4]) = w;
            }
        }
    };

    // ldmatrix per-lane base addresses
    const unsigned as_u = (unsigned)__cvta_generic_to_shared(As);
    const unsigned a_base =
        as_u + (((wr * WM + (lane & 7) + 8 * ((lane >> 3) & 1)) * ASTR +
                 4 * (lane >> 4)) << 2);
    unsigned b_base = 0;
    if (TB) {
        const unsigned bs_u = (unsigned)__cvta_generic_to_shared(Bs);
        const int ml = lane & 15;
        b_base = bs_u + (((wc * WN + (ml & 7)) * 20 + 4 * ((ml >> 3) & 1)) << 2);
    }

    float acc[MT][NT][4];
#pragma unroll
    for (int i = 0; i < MT; i++)
#pragma unroll
        for (int j = 0; j < NT; j++)
#pragma unroll
            for (int e = 0; e < 4; e++) acc[i][j][e] = 0.0f;

    gload(0);
    sstore(0);
    __syncthreads();

    const int nch = K / 16;
    for (int c = 0; c < nch; c++) {
        const int buf = c & 1;
        if (c + 1 < nch) gload((c + 1) * 16);

        const unsigned abp = a_base + buf * (ABUF * 4);
        const unsigned bbp = b_base + buf * (BBUF * 4);
        const float* bbf = Bs + buf * BBUF;
#pragma unroll
        for (int ks = 0; ks < 2; ks++) {
            unsigned afr[MT][4], bfr[NT][2];
#pragma unroll
            for (int i = 0; i < MT; i++)
                ldsm_x4(afr[i], abp + i * (16 * ASTR * 4) + ks * 32);
            if (TB) {
#pragma unroll
                for (int j = 0; j < NT; j++)
                    ldsm_x2(bfr[j], bbp + j * (8 * 20 * 4) + ks * 32);
            } else {
#pragma unroll
                for (int j = 0; j < NT; j++) {
                    int n = wc * WN + j * 8 + g;
                    bfr[j][0] = __float_as_uint(bbf[(ks * 8 + tg) * BSTR + n]);
                    bfr[j][1] = __float_as_uint(bbf[(ks * 8 + 4 + tg) * BSTR + n]);
                }
            }
#pragma unroll
            for (int i = 0; i < MT; i++)
#pragma unroll
                for (int j = 0; j < NT; j++) mma8(acc[i][j], afr[i], bfr[j]);
        }

        if (c + 1 < nch) sstore(buf ^ 1);
        __syncthreads();
    }

    // Epilogue
#pragma unroll
    for (int i = 0; i < MT; i++) {
        int r0 = m0 + wr * WM + i * 16 + g;
#pragma unroll
        for (int j = 0; j < NT; j++) {
            int col = n0 + wc * WN + j * 8 + tg * 2;
            float v0 = acc[i][j][0] * alpha;
            float v1 = acc[i][j][1] * alpha;
            float v2 = acc[i][j][2] * alpha;
            float v3 = acc[i][j][3] * alpha;
            if (epi == 1) {
                v0 = fmaxf(v0, 0.0f); v1 = fmaxf(v1, 0.0f);
                v2 = fmaxf(v2, 0.0f); v3 = fmaxf(v3, 0.0f);
            } else if (epi == 2) {
                v0 += R[(long)r0 * ldc + col];
                v1 += R[(long)r0 * ldc + col + 1];
                v2 += R[(long)(r0 + 8) * ldc + col];
                v3 += R[(long)(r0 + 8) * ldc + col + 1];
            }
            float2 p01; p01.x = v0; p01.y = v1;
            float2 p23; p23.x = v2; p23.y = v3;
            *reinterpret_cast<float2*>(&C[(long)r0 * ldc + col]) = p01;
            *reinterpret_cast<float2*>(&C[(long)(r0 + 8) * ldc + col]) = p23;
        }
    }
}

template <int BM, int BN, bool TB>
__global__ void __launch_bounds__(256, 2)
gemm_mma(const float* __restrict__ A, int lda, long sAb, long sAh,
         const float* __restrict__ Bg, int ldb, long sBb, long sBh,
         float* __restrict__ C, int ldc, long sCb, long sCh,
         const float* __restrict__ R,
         int K, float alpha, int epi, int hdiv) {
    __shared__ float As[2 * BM * 20];
    __shared__ float Bs[TB ? (2 * BN * 20) : (2 * 16 * (BN + 8))];
    const int z = blockIdx.z;
    const int zb = z / hdiv;
    const int zh = z % hdiv;
    gemm_body<BM, BN, TB>(As, Bs,
                          A + (long)zb * sAb + (long)zh * sAh, lda,
                          Bg + (long)zb * sBb + (long)zh * sBh, ldb,
                          C + (long)zb * sCb + (long)zh * sCh, ldc,
                          R, K, alpha, epi);
}

// Fused Q/K/V projection: blockIdx.z selects the weight/output pair.
__global__ void __launch_bounds__(256, 2)
qkv_mma(const float* __restrict__ x,
        const float* __restrict__ Wq, const float* __restrict__ Wk,
        const float* __restrict__ Wv,
        float* __restrict__ q, float* __restrict__ k, float* __restrict__ v) {
    __shared__ float As[2 * 128 * 20];
    __shared__ float Bs[2 * 16 * 136];
    const int z = blockIdx.z;
    const float* W = (z == 0) ? Wq : (z == 1) ? Wk : Wv;
    float* C = (z == 0) ? q : (z == 1) ? k : v;
    gemm_body<128, 128, false>(As, Bs, x, D_, W, D_, C, D_, nullptr, D_, 1.0f, 0);
}

// ---------------------------------------------------------------------------
// In-place row softmax; 128 threads, float4 per thread, shuffle reductions.
// Pad keys (mask==0) -> logit -1e9 -> prob ~0 (matches ref underflow).
// ---------------------------------------------------------------------------
__global__ void __launch_bounds__(128)
softmax_kernel(float* __restrict__ attn, const int* __restrict__ mask) {
    const int row = blockIdx.x;           // b*H*S + h*S + q
    const int b = row >> 12;
    const int t = threadIdx.x;            // 0..127
    float4* p = reinterpret_cast<float4*>(attn + (long)row * S_);
    const int4* mp = reinterpret_cast<const int4*>(mask + b * S_);

    float4 v = p[t];
    int4 mm = mp[t];
    if (mm.x == 0) v.x = -1e9f;
    if (mm.y == 0) v.y = -1e9f;
    if (mm.z == 0) v.z = -1e9f;
    if (mm.w == 0) v.w = -1e9f;

    float mx = fmaxf(fmaxf(v.x, v.y), fmaxf(v.z, v.w));
#pragma unroll
    for (int o = 16; o; o >>= 1) mx = fmaxf(mx, __shfl_xor_sync(0xffffffffu, mx, o));
    __shared__ float sm[4], ss[4];
    if ((t & 31) == 0) sm[t >> 5] = mx;
    __syncthreads();
    mx = fmaxf(fmaxf(sm[0], sm[1]), fmaxf(sm[2], sm[3]));

    float4 e;
    e.x = expf(v.x - mx);
    e.y = expf(v.y - mx);
    e.z = expf(v.z - mx);
    e.w = expf(v.w - mx);
    float s = e.x + e.y + e.z + e.w;
#pragma unroll
    for (int o = 16; o; o >>= 1) s += __shfl_xor_sync(0xffffffffu, s, o);
    if ((t & 31) == 0) ss[t >> 5] = s;
    __syncthreads();
    s = ss[0] + ss[1] + ss[2] + ss[3];
    const float inv = 1.0f / s;
    e.x *= inv; e.y *= inv; e.z *= inv; e.w *= inv;
    p[t] = e;
}

// ---------------------------------------------------------------------------
// LayerNorm over last dim (512)
// ---------------------------------------------------------------------------
__global__ void ln_kernel(const float* __restrict__ in,
                          const float* __restrict__ g,
                          const float* __restrict__ bb,
                          float* __restrict__ out) {
    const int row = blockIdx.x;
    const float* p = in + (long)row * D_;
    const int t = threadIdx.x;

    float x0 = p[t];
    float x1 = p[t + 256];

    __shared__ float red[256];
    red[t] = x0 + x1;
    __syncthreads();
#pragma unroll
    for (int s = 128; s > 0; s >>= 1) {
        if (t < s) red[t] += red[t + s];
        __syncthreads();
    }
    const float mean = red[0] * (1.0f / D_);
    __syncthreads();

    float d0 = x0 - mean;
    float d1 = x1 - mean;
    red[t] = d0 * d0 + d1 * d1;
    __syncthreads();
#pragma unroll
    for (int s = 128; s > 0; s >>= 1) {
        if (t < s) red[t] += red[t + s];
        __syncthreads();
    }
    const float var = red[0] * (1.0f / D_);
    const float rs = rsqrtf(var + 1e-5f);

    float* o = out + (long)row * D_;
    o[t] = d0 * rs * g[t] + bb[t];
    o[t + 256] = d1 * rs * g[t + 256] + bb[t + 256];
}

// ---------------------------------------------------------------------------
extern "C" void kernel_launch(void* const* d_in, const int* in_sizes, int n_in,
                              void* d_out, int out_size) {
    const float* enc = (const float*)d_in[0];
    const int* mask = (const int*)d_in[1];
    const float* Wq = (const float*)d_in[2];
    const float* Wk = (const float*)d_in[3];
    const float* Wv = (const float*)d_in[4];
    const float* Wo = (const float*)d_in[5];
    const float* ln1g = (const float*)d_in[6];
    const float* ln1b = (const float*)d_in[7];
    const float* W1 = (const float*)d_in[8];
    const float* W2 = (const float*)d_in[9];
    const float* ln2g = (const float*)d_in[10];
    const float* ln2b = (const float*)d_in[11];

    float *x, *q, *k, *v, *ctx, *tmp, *h1, *pos;
    cudaGetSymbolAddress((void**)&x, g_x);
    cudaGetSymbolAddress((void**)&q, g_q);
    cudaGetSymbolAddress((void**)&k, g_k);
    cudaGetSymbolAddress((void**)&v, g_v);
    cudaGetSymbolAddress((void**)&ctx, g_ctx);
    cudaGetSymbolAddress((void**)&tmp, g_tmp);
    cudaGetSymbolAddress((void**)&h1, g_h1);
    cudaGetSymbolAddress((void**)&pos, g_pos);

    float* out_x = (float*)d_out;
    float* out_attn = out_x + X_ELEMS;

    pos_kernel<<<(S_ * D_ + 255) / 256, 256>>>(pos);
    add_pos_kernel<<<(X_ELEMS + 255) / 256, 256>>>(x, enc, pos);

    const long WLD = (long)D_ * D_;
    const long WF = (long)D_ * DFF_;

    for (int l = 0; l < L_; l++) {
        const float* Wo_l = Wo + l * WLD;
        const float* W1_l = W1 + l * WF;
        const float* W2_l = W2 + l * WF;
        float* attn_l = out_attn + (long)l * ATTN_PER_LAYER;

        // Fused Q,K,V projections: [4096,512] @ [512,512] x3
        qkv_mma<<<dim3(4, 32, 3), 256>>>(x, Wq + l * WLD, Wk + l * WLD, Wv + l * WLD,
                                         q, k, v);

        // Scores: per (b,h): Q[512,64] @ K^T * (1/8) -> attn region
        gemm_mma<128, 128, true><<<dim3(4, 4, B_ * H_), 256>>>(
            q, D_, (long)S_ * D_, DK_,
            k, D_, (long)S_ * D_, DK_,
            attn_l, S_, (long)H_ * S_ * S_, (long)S_ * S_,
            nullptr, DK_, 0.125f, 0, H_);

        // Softmax (in place, applies pad mask)
        softmax_kernel<<<B_ * H_ * S_, 128>>>(attn_l, mask);

        // ctx: per (b,h): attn[512,512] @ V[512,64] -> [B,S,H,DV]
        gemm_mma<128, 64, false><<<dim3(1, 4, B_ * H_), 256>>>(
            attn_l, S_, (long)H_ * S_ * S_, (long)S_ * S_,
            v, D_, (long)S_ * D_, DV_,
            ctx, D_, (long)S_ * D_, DV_,
            nullptr, S_, 1.0f, 0, H_);

        // Wo projection + residual, then LN1
        gemm_mma<128, 128, false><<<dim3(4, 32, 1), 256>>>(
            ctx, D_, 0, 0, Wo_l, D_, 0, 0, tmp, D_, 0, 0, x, D_, 1.0f, 2, 1);
        ln_kernel<<<M_, 256>>>(tmp, ln1g + l * D_, ln1b + l * D_, x);

        // FFN: relu(x @ W1) @ W2 + x, then LN2
        gemm_mma<128, 128, false><<<dim3(16, 32, 1), 256>>>(
            x, D_, 0, 0, W1_l, DFF_, 0, 0, h1, DFF_, 0, 0, nullptr, D_, 1.0f, 1, 1);
        gemm_mma<128, 128, false><<<dim3(4, 32, 1), 256>>>(
            h1, DFF_, 0, 0, W2_l, D_, 0, 0, tmp, D_, 0, 0, x, DFF_, 1.0f, 2, 1);
        ln_kernel<<<M_, 256>>>(tmp, ln2g + l * D_, ln2b + l * D_, x);
    }

    cudaMemcpyAsync(out_x, x, (size_t)X_ELEMS * sizeof(float),
                    cudaMemcpyDeviceToDevice, 0);
}

// round 4
// speedup vs baseline: 3.5381x; 1.1343x over previous
#include <cuda_runtime.h>
#include <math.h>

// Problem constants
#define B_ 8
#define S_ 512
#define D_ 512
#define H_ 8
#define DK_ 64
#define DV_ 64
#define DFF_ 2048
#define L_ 6
#define M_ (B_ * S_)               // 4096 rows
#define X_ELEMS (M_ * D_)          // 2,097,152
#define ATTN_PER_LAYER ((long)B_ * H_ * S_ * S_)  // 16,777,216

// Device scratch (allocations are forbidden; use __device__ globals)
__device__ float g_x[X_ELEMS];
__device__ float g_q[X_ELEMS];
__device__ float g_k[X_ELEMS];
__device__ float g_v[X_ELEMS];
__device__ float g_ctx[X_ELEMS];
__device__ float g_tmp[X_ELEMS];
__device__ float g_h1[M_ * DFF_];
__device__ float g_pos[S_ * D_];

// ---------------------------------------------------------------------------
// tf32 / mma / ldmatrix / cp.async helpers
// ---------------------------------------------------------------------------
__device__ __forceinline__ unsigned tfc(unsigned x) {
    unsigned r;
    asm("cvt.rna.tf32.f32 %0, %1;" : "=r"(r) : "f"(__uint_as_float(x)));
    return r;
}

__device__ __forceinline__ void mma8(float* d, const unsigned* a, const unsigned* b) {
    asm volatile(
        "mma.sync.aligned.m16n8k8.row.col.f32.tf32.tf32.f32 "
        "{%0,%1,%2,%3}, {%4,%5,%6,%7}, {%8,%9}, {%0,%1,%2,%3};"
        : "+f"(d[0]), "+f"(d[1]), "+f"(d[2]), "+f"(d[3])
        : "r"(a[0]), "r"(a[1]), "r"(a[2]), "r"(a[3]), "r"(b[0]), "r"(b[1]));
}

__device__ __forceinline__ void ldsm_x4(unsigned* r, unsigned addr) {
    asm volatile("ldmatrix.sync.aligned.m8n8.x4.shared.b16 {%0,%1,%2,%3}, [%4];"
                 : "=r"(r[0]), "=r"(r[1]), "=r"(r[2]), "=r"(r[3]) : "r"(addr));
}

__device__ __forceinline__ void cpa16(unsigned dst, const void* src) {
    asm volatile("cp.async.cg.shared.global [%0], [%1], 16;" :: "r"(dst), "l"(src));
}
__device__ __forceinline__ void cpa_commit() {
    asm volatile("cp.async.commit_group;" ::: "memory");
}
template <int N>
__device__ __forceinline__ void cpa_wait() {
    asm volatile("cp.async.wait_group %0;" :: "n"(N) : "memory");
}

// ---------------------------------------------------------------------------
// Positional table (double precision to match numpy float64 path)
// ---------------------------------------------------------------------------
__global__ void pos_kernel(float* __restrict__ pos) {
    int idx = blockIdx.x * blockDim.x + threadIdx.x;
    if (idx >= S_ * D_) return;
    int s = idx >> 9;
    int d = idx & 511;
    double val = 0.0;
    if (s > 0) {
        double ang = (double)s * exp(-log(10000.0) * (2.0 * (double)d / (double)D_));
        val = (d & 1) ? cos(ang) : sin(ang);
    }
    pos[idx] = (float)val;
}

__global__ void add_pos_kernel(float* __restrict__ x,
                               const float* __restrict__ enc,
                               const float* __restrict__ pos) {
    int idx = blockIdx.x * blockDim.x + threadIdx.x;
    if (idx >= X_ELEMS) return;
    int sd = idx & (S_ * D_ - 1);
    x[idx] = enc[idx] + pos[sd];
}

// ---------------------------------------------------------------------------
// TF32 tensor-core GEMM body, 4-stage cp.async pipeline.
//   C[m,n] = alpha * sum_k A[m,k] * (TB ? B[n,k] : B[k,n])  (+ epilogue)
// Block: 256 threads (8 warps, 2 x 4). Warp tile: (BM/2) x (BN/4).
// Smem holds raw fp32; fragments converted to tf32 (cvt.rna) post-ldmatrix.
// A smem: row-major [BM][16] stride 20. B smem: TB -> [BN][16] stride 20
// (ldmatrix.x4); !TB -> [16][BN+8] (scalar conflict-free LDS).
// epi: 0 = none, 1 = relu, 2 = += R[m*ldc+n]
// ---------------------------------------------------------------------------
template <int BM, int BN, bool TB, int STAGES>
struct GCfg {
    static constexpr int ASTR = 20;
    static constexpr int ABUF = BM * ASTR;
    static constexpr int BSTR = TB ? 20 : (BN + 8);
    static constexpr int BBUF = TB ? (BN * 20) : (16 * BSTR);
    static constexpr int SMEM_BYTES = STAGES * (ABUF + BBUF) * 4;
};

template <int BM, int BN, bool TB, int STAGES>
__device__ __forceinline__ void gemm_body(
    float* __restrict__ smem,
    const float* __restrict__ A, int lda,
    const float* __restrict__ Bg, int ldb,
    float* __restrict__ C, int ldc,
    const float* __restrict__ R,
    int K, float alpha, int epi) {
    using CF = GCfg<BM, BN, TB, STAGES>;
    constexpr int ASTR = CF::ASTR, ABUF = CF::ABUF;
    constexpr int BSTR = CF::BSTR, BBUF = CF::BBUF;
    constexpr int AF = (BM * 16) / (4 * 256);
    constexpr int BF = (BN * 16) / (4 * 256);
    constexpr int WM = BM / 2, WN = BN / 4;
    constexpr int MT = WM / 16, NT = WN / 8;

    const int tid = threadIdx.x;
    const int lane = tid & 31;
    const int warp = tid >> 5;
    const int g = lane >> 2;
    const int tg = lane & 3;
    const int wr = warp & 1;
    const int wc = warp >> 1;
    const int m0 = blockIdx.y * BM;
    const int n0 = blockIdx.x * BN;

    float* As = smem;
    float* Bs = smem + STAGES * ABUF;
    const unsigned as_u = (unsigned)__cvta_generic_to_shared(As);
    const unsigned bs_u = (unsigned)__cvta_generic_to_shared(Bs);

    // async load of one 16-K stage
    auto load_stage = [&](int slot, int k0) {
        unsigned ab = as_u + (unsigned)(slot * ABUF) * 4u;
#pragma unroll
        for (int it = 0; it < AF; it++) {
            int f = tid + it * 256;
            int row = f >> 2, c4 = f & 3;
            cpa16(ab + (unsigned)(row * ASTR + c4 * 4) * 4u,
                  &A[(long)(m0 + row) * lda + k0 + c4 * 4]);
        }
        unsigned bb = bs_u + (unsigned)(slot * BBUF) * 4u;
#pragma unroll
        for (int it = 0; it < BF; it++) {
            int f = tid + it * 256;
            if (TB) {
                int n = f >> 2, k4 = f & 3;
                cpa16(bb + (unsigned)(n * 20 + k4 * 4) * 4u,
                      &Bg[(long)(n0 + n) * ldb + k0 + k4 * 4]);
            } else {
                int row = f / (BN / 4), c4 = f % (BN / 4);
                cpa16(bb + (unsigned)(row * BSTR + c4 * 4) * 4u,
                      &Bg[(long)(k0 + row) * ldb + n0 + c4 * 4]);
            }
        }
    };

    // ldmatrix per-lane base addresses
    const unsigned a_base =
        as_u + (unsigned)(((wr * WM + (lane & 7) + 8 * ((lane >> 3) & 1)) * ASTR +
                           4 * (lane >> 4)) << 2);
    unsigned b_base = 0;
    if (TB) {
        b_base = bs_u + (unsigned)(((wc * WN + (lane & 7) + 8 * (lane >> 4)) * 20 +
                                    4 * ((lane >> 3) & 1)) << 2);
    }

    float acc[MT][NT][4];
#pragma unroll
    for (int i = 0; i < MT; i++)
#pragma unroll
        for (int j = 0; j < NT; j++)
#pragma unroll
            for (int e = 0; e < 4; e++) acc[i][j][e] = 0.0f;

    const int nch = K / 16;
#pragma unroll
    for (int s = 0; s < STAGES - 1; s++) {
        if (s < nch) load_stage(s, s * 16);
        cpa_commit();
    }

    for (int c = 0; c < nch; c++) {
        cpa_wait<STAGES - 2>();
        __syncthreads();
        const int buf = c % STAGES;
        const unsigned abp = a_base + (unsigned)(buf * ABUF) * 4u;
        const unsigned bbp = b_base + (unsigned)(buf * BBUF) * 4u;
        const float* bbf = Bs + buf * BBUF;

#pragma unroll
        for (int ks = 0; ks < 2; ks++) {
            unsigned afr[MT][4], bfr[NT][2];
#pragma unroll
            for (int i = 0; i < MT; i++) {
                ldsm_x4(afr[i], abp + i * (16 * ASTR * 4) + ks * 32);
#pragma unroll
                for (int e = 0; e < 4; e++) afr[i][e] = tfc(afr[i][e]);
            }
            if (TB) {
#pragma unroll
                for (int j = 0; j < NT; j += 2)
                    ldsm_x4(&bfr[j][0], bbp + j * (8 * 20 * 4) + ks * 32);
            } else {
#pragma unroll
                for (int j = 0; j < NT; j++) {
                    int n = wc * WN + j * 8 + g;
                    bfr[j][0] = __float_as_uint(bbf[(ks * 8 + tg) * BSTR + n]);
                    bfr[j][1] = __float_as_uint(bbf[(ks * 8 + 4 + tg) * BSTR + n]);
                }
            }
#pragma unroll
            for (int j = 0; j < NT; j++) {
                bfr[j][0] = tfc(bfr[j][0]);
                bfr[j][1] = tfc(bfr[j][1]);
            }
#pragma unroll
            for (int i = 0; i < MT; i++)
#pragma unroll
                for (int j = 0; j < NT; j++) mma8(acc[i][j], afr[i], bfr[j]);
        }

        const int p = c + STAGES - 1;
        if (p < nch) load_stage(p % STAGES, p * 16);
        cpa_commit();
    }

    // Epilogue
#pragma unroll
    for (int i = 0; i < MT; i++) {
        int r0 = m0 + wr * WM + i * 16 + g;
#pragma unroll
        for (int j = 0; j < NT; j++) {
            int col = n0 + wc * WN + j * 8 + tg * 2;
            float v0 = acc[i][j][0] * alpha;
            float v1 = acc[i][j][1] * alpha;
            float v2 = acc[i][j][2] * alpha;
            float v3 = acc[i][j][3] * alpha;
            if (epi == 1) {
                v0 = fmaxf(v0, 0.0f); v1 = fmaxf(v1, 0.0f);
                v2 = fmaxf(v2, 0.0f); v3 = fmaxf(v3, 0.0f);
            } else if (epi == 2) {
                v0 += R[(long)r0 * ldc + col];
                v1 += R[(long)r0 * ldc + col + 1];
                v2 += R[(long)(r0 + 8) * ldc + col];
                v3 += R[(long)(r0 + 8) * ldc + col + 1];
            }
            float2 p01; p01.x = v0; p01.y = v1;
            float2 p23; p23.x = v2; p23.y = v3;
            *reinterpret_cast<float2*>(&C[(long)r0 * ldc + col]) = p01;
            *reinterpret_cast<float2*>(&C[(long)(r0 + 8) * ldc + col]) = p23;
        }
    }
}

template <int BM, int BN, bool TB, int STAGES>
__global__ void __launch_bounds__(256, 2)
gemm_cp(const float* __restrict__ A, int lda, long sAb, long sAh,
        const float* __restrict__ Bg, int ldb, long sBb, long sBh,
        float* __restrict__ C, int ldc, long sCb, long sCh,
        const float* __restrict__ R,
        int K, float alpha, int epi, int hdiv) {
    extern __shared__ float smem[];
    const int z = blockIdx.z;
    const int zb = z / hdiv;
    const int zh = z % hdiv;
    gemm_body<BM, BN, TB, STAGES>(smem,
                                  A + (long)zb * sAb + (long)zh * sAh, lda,
                                  Bg + (long)zb * sBb + (long)zh * sBh, ldb,
                                  C + (long)zb * sCb + (long)zh * sCh, ldc,
                                  R, K, alpha, epi);
}

// Fused Q/K/V projection: blockIdx.z selects the weight/output pair.
__global__ void __launch_bounds__(256, 2)
qkv_cp(const float* __restrict__ x,
       const float* __restrict__ Wq, const float* __restrict__ Wk,
       const float* __restrict__ Wv,
       float* __restrict__ q, float* __restrict__ k, float* __restrict__ v) {
    extern __shared__ float smem[];
    const int z = blockIdx.z;
    const float* W = (z == 0) ? Wq : (z == 1) ? Wk : Wv;
    float* C = (z == 0) ? q : (z == 1) ? k : v;
    gemm_body<128, 128, false, 4>(smem, x, D_, W, D_, C, D_, nullptr, D_, 1.0f, 0);
}

// ---------------------------------------------------------------------------
// In-place row softmax; 128 threads, float4 per thread, shuffle reductions.
// ---------------------------------------------------------------------------
__global__ void __launch_bounds__(128)
softmax_kernel(float* __restrict__ attn, const int* __restrict__ mask) {
    const int row = blockIdx.x;
    const int b = row >> 12;
    const int t = threadIdx.x;
    float4* p = reinterpret_cast<float4*>(attn + (long)row * S_);
    const int4* mp = reinterpret_cast<const int4*>(mask + b * S_);

    float4 v = p[t];
    int4 mm = mp[t];
    if (mm.x == 0) v.x = -1e9f;
    if (mm.y == 0) v.y = -1e9f;
    if (mm.z == 0) v.z = -1e9f;
    if (mm.w == 0) v.w = -1e9f;

    float mx = fmaxf(fmaxf(v.x, v.y), fmaxf(v.z, v.w));
#pragma unroll
    for (int o = 16; o; o >>= 1) mx = fmaxf(mx, __shfl_xor_sync(0xffffffffu, mx, o));
    __shared__ float sm[4], ss[4];
    if ((t & 31) == 0) sm[t >> 5] = mx;
    __syncthreads();
    mx = fmaxf(fmaxf(sm[0], sm[1]), fmaxf(sm[2], sm[3]));

    float4 e;
    e.x = expf(v.x - mx);
    e.y = expf(v.y - mx);
    e.z = expf(v.z - mx);
    e.w = expf(v.w - mx);
    float s = e.x + e.y + e.z + e.w;
#pragma unroll
    for (int o = 16; o; o >>= 1) s += __shfl_xor_sync(0xffffffffu, s, o);
    if ((t & 31) == 0) ss[t >> 5] = s;
    __syncthreads();
    s = ss[0] + ss[1] + ss[2] + ss[3];
    const float inv = 1.0f / s;
    e.x *= inv; e.y *= inv; e.z *= inv; e.w *= inv;
    p[t] = e;
}

// ---------------------------------------------------------------------------
// LayerNorm over last dim (512)
// ---------------------------------------------------------------------------
__global__ void ln_kernel(const float* __restrict__ in,
                          const float* __restrict__ g,
                          const float* __restrict__ bb,
                          float* __restrict__ out) {
    const int row = blockIdx.x;
    const float* p = in + (long)row * D_;
    const int t = threadIdx.x;

    float x0 = p[t];
    float x1 = p[t + 256];

    __shared__ float red[256];
    red[t] = x0 + x1;
    __syncthreads();
#pragma unroll
    for (int s = 128; s > 0; s >>= 1) {
        if (t < s) red[t] += red[t + s];
        __syncthreads();
    }
    const float mean = red[0] * (1.0f / D_);
    __syncthreads();

    float d0 = x0 - mean;
    float d1 = x1 - mean;
    red[t] = d0 * d0 + d1 * d1;
    __syncthreads();
#pragma unroll
    for (int s = 128; s > 0; s >>= 1) {
        if (t < s) red[t] += red[t + s];
        __syncthreads();
    }
    const float var = red[0] * (1.0f / D_);
    const float rs = rsqrtf(var + 1e-5f);

    float* o = out + (long)row * D_;
    o[t] = d0 * rs * g[t] + bb[t];
    o[t + 256] = d1 * rs * g[t + 256] + bb[t + 256];
}

// ---------------------------------------------------------------------------
extern "C" void kernel_launch(void* const* d_in, const int* in_sizes, int n_in,
                              void* d_out, int out_size) {
    const float* enc = (const float*)d_in[0];
    const int* mask = (const int*)d_in[1];
    const float* Wq = (const float*)d_in[2];
    const float* Wk = (const float*)d_in[3];
    const float* Wv = (const float*)d_in[4];
    const float* Wo = (const float*)d_in[5];
    const float* ln1g = (const float*)d_in[6];
    const float* ln1b = (const float*)d_in[7];
    const float* W1 = (const float*)d_in[8];
    const float* W2 = (const float*)d_in[9];
    const float* ln2g = (const float*)d_in[10];
    const float* ln2b = (const float*)d_in[11];

    float *x, *q, *k, *v, *ctx, *tmp, *h1, *pos;
    cudaGetSymbolAddress((void**)&x, g_x);
    cudaGetSymbolAddress((void**)&q, g_q);
    cudaGetSymbolAddress((void**)&k, g_k);
    cudaGetSymbolAddress((void**)&v, g_v);
    cudaGetSymbolAddress((void**)&ctx, g_ctx);
    cudaGetSymbolAddress((void**)&tmp, g_tmp);
    cudaGetSymbolAddress((void**)&h1, g_h1);
    cudaGetSymbolAddress((void**)&pos, g_pos);

    float* out_x = (float*)d_out;
    float* out_attn = out_x + X_ELEMS;

    // Dynamic smem opt-in (idempotent; host-side attribute, not captured)
    constexpr int SM_PROJ = GCfg<128, 128, false, 4>::SMEM_BYTES;  // 75776
    constexpr int SM_SCOR = GCfg<128, 128, true, 4>::SMEM_BYTES;   // 81920
    constexpr int SM_CTX  = GCfg<128, 64, false, 4>::SMEM_BYTES;   // 59392
    cudaFuncSetAttribute(gemm_cp<128, 128, false, 4>,
                         cudaFuncAttributeMaxDynamicSharedMemorySize, SM_PROJ);
    cudaFuncSetAttribute(gemm_cp<128, 128, true, 4>,
                         cudaFuncAttributeMaxDynamicSharedMemorySize, SM_SCOR);
    cudaFuncSetAttribute(gemm_cp<128, 64, false, 4>,
                         cudaFuncAttributeMaxDynamicSharedMemorySize, SM_CTX);
    cudaFuncSetAttribute(qkv_cp,
                         cudaFuncAttributeMaxDynamicSharedMemorySize, SM_PROJ);

    pos_kernel<<<(S_ * D_ + 255) / 256, 256>>>(pos);
    add_pos_kernel<<<(X_ELEMS + 255) / 256, 256>>>(x, enc, pos);

    const long WLD = (long)D_ * D_;
    const long WF = (long)D_ * DFF_;

    for (int l = 0; l < L_; l++) {
        const float* Wo_l = Wo + l * WLD;
        const float* W1_l = W1 + l * WF;
        const float* W2_l = W2 + l * WF;
        float* attn_l = out_attn + (long)l * ATTN_PER_LAYER;

        // Fused Q,K,V projections: [4096,512] @ [512,512] x3
        qkv_cp<<<dim3(4, 32, 3), 256, SM_PROJ>>>(
            x, Wq + l * WLD, Wk + l * WLD, Wv + l * WLD, q, k, v);

        // Scores: per (b,h): Q[512,64] @ K^T * (1/8) -> attn region
        gemm_cp<128, 128, true, 4><<<dim3(4, 4, B_ * H_), 256, SM_SCOR>>>(
            q, D_, (long)S_ * D_, DK_,
            k, D_, (long)S_ * D_, DK_,
            attn_l, S_, (long)H_ * S_ * S_, (long)S_ * S_,
            nullptr, DK_, 0.125f, 0, H_);

        // Softmax (in place, applies pad mask)
        softmax_kernel<<<B_ * H_ * S_, 128>>>(attn_l, mask);

        // ctx: per (b,h): attn[512,512] @ V[512,64] -> [B,S,H,DV]
        gemm_cp<128, 64, false, 4><<<dim3(1, 4, B_ * H_), 256, SM_CTX>>>(
            attn_l, S_, (long)H_ * S_ * S_, (long)S_ * S_,
            v, D_, (long)S_ * D_, DV_,
            ctx, D_, (long)S_ * D_, DV_,
            nullptr, S_, 1.0f, 0, H_);

        // Wo projection + residual, then LN1
        gemm_cp<128, 128, false, 4><<<dim3(4, 32, 1), 256, SM_PROJ>>>(
            ctx, D_, 0, 0, Wo_l, D_, 0, 0, tmp, D_, 0, 0, x, D_, 1.0f, 2, 1);
        ln_kernel<<<M_, 256>>>(tmp, ln1g + l * D_, ln1b + l * D_, x);

        // FFN: relu(x @ W1) @ W2 + x, then LN2
        gemm_cp<128, 128, false, 4><<<dim3(16, 32, 1), 256, SM_PROJ>>>(
            x, D_, 0, 0, W1_l, DFF_, 0, 0, h1, DFF_, 0, 0, nullptr, D_, 1.0f, 1, 1);
        gemm_cp<128, 128, false, 4><<<dim3(4, 32, 1), 256, SM_PROJ>>>(
            h1, DFF_, 0, 0, W2_l, D_, 0, 0, tmp, D_, 0, 0, x, DFF_, 1.0f, 2, 1);
        ln_kernel<<<M_, 256>>>(tmp, ln2g + l * D_, ln2b + l * D_, x);
    }

    cudaMemcpyAsync(out_x, x, (size_t)X_ELEMS * sizeof(float),
                    cudaMemcpyDeviceToDevice, 0);
}

// round 6
// speedup vs baseline: 4.0022x; 1.1312x over previous
#include <cuda_runtime.h>
#include <math.h>

// Problem constants
#define B_ 8
#define S_ 512
#define D_ 512
#define H_ 8
#define DK_ 64
#define DV_ 64
#define DFF_ 2048
#define L_ 6
#define M_ (B_ * S_)               // 4096 rows
#define X_ELEMS (M_ * D_)          // 2,097,152
#define ATTN_PER_LAYER ((long)B_ * H_ * S_ * S_)  // 16,777,216
#define WLD (D_ * D_)              // 262144
#define WF (D_ * DFF_)             // 1048576

// Device scratch (allocations are forbidden; use __device__ globals)
__device__ float g_x[X_ELEMS];
__device__ float g_xr[X_ELEMS];    // tf32-rounded copy of x (GEMM A input)
__device__ float g_q[X_ELEMS];
__device__ float g_k[X_ELEMS];
__device__ float g_v[X_ELEMS];
__device__ float g_ctx[X_ELEMS];
__device__ float g_tmp[X_ELEMS];
__device__ float g_h1[M_ * DFF_];
__device__ float g_pos[S_ * D_];
__device__ float g_wr[6 * (4 * WLD + 2 * WF)];  // tf32-rounded weights (75.5 MB)

// ---------------------------------------------------------------------------
// helpers
// ---------------------------------------------------------------------------
__device__ __forceinline__ unsigned tfc(unsigned x) {
    unsigned r;
    asm("cvt.rna.tf32.f32 %0, %1;" : "=r"(r) : "f"(__uint_as_float(x)));
    return r;
}
__device__ __forceinline__ float frnd(float x) {
    return __uint_as_float(tfc(__float_as_uint(x)));
}

__device__ __forceinline__ void mma8(float* d, const unsigned* a, const unsigned* b) {
    asm volatile(
        "mma.sync.aligned.m16n8k8.row.col.f32.tf32.tf32.f32 "
        "{%0,%1,%2,%3}, {%4,%5,%6,%7}, {%8,%9}, {%0,%1,%2,%3};"
        : "+f"(d[0]), "+f"(d[1]), "+f"(d[2]), "+f"(d[3])
        : "r"(a[0]), "r"(a[1]), "r"(a[2]), "r"(a[3]), "r"(b[0]), "r"(b[1]));
}

__device__ __forceinline__ void ldsm_x4(unsigned* r, unsigned addr) {
    asm volatile("ldmatrix.sync.aligned.m8n8.x4.shared.b16 {%0,%1,%2,%3}, [%4];"
                 : "=r"(r[0]), "=r"(r[1]), "=r"(r[2]), "=r"(r[3]) : "r"(addr));
}

__device__ __forceinline__ void cpa16(unsigned dst, const void* src) {
    asm volatile("cp.async.cg.shared.global [%0], [%1], 16;" :: "r"(dst), "l"(src));
}
__device__ __forceinline__ void cpa_commit() {
    asm volatile("cp.async.commit_group;" ::: "memory");
}
template <int N>
__device__ __forceinline__ void cpa_wait() {
    asm volatile("cp.async.wait_group %0;" :: "n"(N) : "memory");
}

// ---------------------------------------------------------------------------
// tf32 rounding copy (for weights): out[i] = rna_tf32(in[i])
// ---------------------------------------------------------------------------
__global__ void round_kernel(const float4* __restrict__ in,
                             float4* __restrict__ out, int n4) {
    int i = blockIdx.x * blockDim.x + threadIdx.x;
    if (i >= n4) return;
    float4 v = in[i];
    v.x = frnd(v.x); v.y = frnd(v.y); v.z = frnd(v.z); v.w = frnd(v.w);
    out[i] = v;
}

// ---------------------------------------------------------------------------
// Positional table (double precision to match numpy float64 path)
// ---------------------------------------------------------------------------
__global__ void pos_kernel(float* __restrict__ pos) {
    int idx = blockIdx.x * blockDim.x + threadIdx.x;
    if (idx >= S_ * D_) return;
    int s = idx >> 9;
    int d = idx & 511;
    double val = 0.0;
    if (s > 0) {
        double ang = (double)s * exp(-log(10000.0) * (2.0 * (double)d / (double)D_));
        val = (d & 1) ? cos(ang) : sin(ang);
    }
    pos[idx] = (float)val;
}

__global__ void add_pos_kernel(float* __restrict__ x, float* __restrict__ xr,
                               const float* __restrict__ enc,
                               const float* __restrict__ pos) {
    int idx = blockIdx.x * blockDim.x + threadIdx.x;
    if (idx >= X_ELEMS) return;
    int sd = idx & (S_ * D_ - 1);
    float v = enc[idx] + pos[sd];
    x[idx] = v;
    xr[idx] = frnd(v);
}

// ---------------------------------------------------------------------------
// TF32 tensor-core GEMM, 4-stage cp.async pipeline.
//   C[m,n] = alpha * sum_k A[m,k] * (TB ? B[n,k] : B[k,n])  (+ epilogue)
// Inputs are pre-rounded to tf32 (bit-exact under hardware truncation),
// except when CVTA=true: A fragments get cvt.rna after ldmatrix.
// ROUT=true: round outputs to tf32 (producer-side rounding for chained GEMMs).
// epi: 0 = none, 1 = relu, 2 = += R[m*ldc+n]
// ---------------------------------------------------------------------------
template <int BM, int BN, bool TB, int STAGES>
struct GCfg {
    static constexpr int ASTR = 20;
    static constexpr int ABUF = BM * ASTR;
    static constexpr int BSTR = TB ? 20 : (BN + 8);
    static constexpr int BBUF = TB ? (BN * 20) : (16 * BSTR);
    static constexpr int SMEM_BYTES = STAGES * (ABUF + BBUF) * 4;
};

template <int BM, int BN, bool TB, int STAGES, bool CVTA, bool ROUT>
__device__ __forceinline__ void gemm_body(
    float* __restrict__ smem,
    const float* __restrict__ A, int lda,
    const float* __restrict__ Bg, int ldb,
    float* __restrict__ C, int ldc,
    const float* __restrict__ R,
    int K, float alpha, int epi) {
    using CF = GCfg<BM, BN, TB, STAGES>;
    constexpr int ASTR = CF::ASTR, ABUF = CF::ABUF;
    constexpr int BSTR = CF::BSTR, BBUF = CF::BBUF;
    constexpr int AF = (BM * 16) / (4 * 256);
    constexpr int BF = (BN * 16) / (4 * 256);
    constexpr int WM = BM / 2, WN = BN / 4;
    constexpr int MT = WM / 16, NT = WN / 8;

    const int tid = threadIdx.x;
    const int lane = tid & 31;
    const int warp = tid >> 5;
    const int g = lane >> 2;
    const int tg = lane & 3;
    const int wr = warp & 1;
    const int wc = warp >> 1;
    const int m0 = blockIdx.y * BM;
    const int n0 = blockIdx.x * BN;

    float* As = smem;
    float* Bs = smem + STAGES * ABUF;
    const unsigned as_u = (unsigned)__cvta_generic_to_shared(As);
    const unsigned bs_u = (unsigned)__cvta_generic_to_shared(Bs);

    // ---- hoisted per-thread copy descriptors ----
    const float* pA[AF];
    unsigned aoff[AF];
#pragma unroll
    for (int it = 0; it < AF; it++) {
        int f = tid + it * 256;
        int row = f >> 2, c4 = f & 3;
        pA[it] = A + (long)(m0 + row) * lda + c4 * 4;
        aoff[it] = as_u + (unsigned)(row * ASTR + c4 * 4) * 4u;
    }
    const float* pB[BF];
    unsigned boff[BF];
    const long stepB = TB ? 16 : (long)16 * ldb;
#pragma unroll
    for (int it = 0; it < BF; it++) {
        int f = tid + it * 256;
        if (TB) {
            int n = f >> 2, k4 = f & 3;
            pB[it] = Bg + (long)(n0 + n) * ldb + k4 * 4;
            boff[it] = bs_u + (unsigned)(n * 20 + k4 * 4) * 4u;
        } else {
            int row = f / (BN / 4), c4 = f % (BN / 4);
            pB[it] = Bg + (long)row * ldb + n0 + c4 * 4;
            boff[it] = bs_u + (unsigned)(row * BSTR + c4 * 4) * 4u;
        }
    }

    int slot_ld = 0;
    auto load_stage = [&]() {
        const unsigned ao = (unsigned)(slot_ld * ABUF) * 4u;
        const unsigned bo = (unsigned)(slot_ld * BBUF) * 4u;
#pragma unroll
        for (int it = 0; it < AF; it++) {
            cpa16(aoff[it] + ao, pA[it]);
            pA[it] += 16;
        }
#pragma unroll
        for (int it = 0; it < BF; it++) {
            cpa16(boff[it] + bo, pB[it]);
            pB[it] += stepB;
        }
        slot_ld = (slot_ld + 1 == STAGES) ? 0 : slot_ld + 1;
    };

    // ldmatrix per-lane base addresses
    const unsigned a_base =
        as_u + (unsigned)(((wr * WM + (lane & 7) + 8 * ((lane >> 3) & 1)) * ASTR +
                           4 * (lane >> 4)) << 2);
    unsigned b_base = 0;
    if (TB) {
        b_base = bs_u + (unsigned)(((wc * WN + (lane & 7) + 8 * (lane >> 4)) * 20 +
                                    4 * ((lane >> 3) & 1)) << 2);
    }

    float acc[MT][NT][4];
#pragma unroll
    for (int i = 0; i < MT; i++)
#pragma unroll
        for (int j = 0; j < NT; j++)
#pragma unroll
            for (int e = 0; e < 4; e++) acc[i][j][e] = 0.0f;

    const int nch = K / 16;
#pragma unroll
    for (int s = 0; s < STAGES - 1; s++) {
        if (s < nch) load_stage();
        cpa_commit();
    }

    int slot_cmp = 0;
    for (int c = 0; c < nch; c++) {
        cpa_wait<STAGES - 2>();
        __syncthreads();
        const unsigned abp = a_base + (unsigned)(slot_cmp * ABUF) * 4u;
        const unsigned bbp = b_base + (unsigned)(slot_cmp * BBUF) * 4u;
        const float* bbf = Bs + slot_cmp * BBUF;
        slot_cmp = (slot_cmp + 1 == STAGES) ? 0 : slot_cmp + 1;

#pragma unroll
        for (int ks = 0; ks < 2; ks++) {
            unsigned afr[MT][4], bfr[NT][2];
#pragma unroll
            for (int i = 0; i < MT; i++) {
                ldsm_x4(afr[i], abp + i * (16 * ASTR * 4) + ks * 32);
                if (CVTA) {
#pragma unroll
                    for (int e = 0; e < 4; e++) afr[i][e] = tfc(afr[i][e]);
                }
            }
            if (TB) {
#pragma unroll
                for (int j = 0; j < NT; j += 2)
                    ldsm_x4(&bfr[j][0], bbp + j * (8 * 20 * 4) + ks * 32);
            } else {
#pragma unroll
                for (int j = 0; j < NT; j++) {
                    int n = wc * WN + j * 8 + g;
                    bfr[j][0] = __float_as_uint(bbf[(ks * 8 + tg) * BSTR + n]);
                    bfr[j][1] = __float_as_uint(bbf[(ks * 8 + 4 + tg) * BSTR + n]);
                }
            }
#pragma unroll
            for (int i = 0; i < MT; i++)
#pragma unroll
                for (int j = 0; j < NT; j++) mma8(acc[i][j], afr[i], bfr[j]);
        }

        if (c + STAGES - 1 < nch) load_stage();
        cpa_commit();
    }

    // Epilogue
#pragma unroll
    for (int i = 0; i < MT; i++) {
        int r0 = m0 + wr * WM + i * 16 + g;
#pragma unroll
        for (int j = 0; j < NT; j++) {
            int col = n0 + wc * WN + j * 8 + tg * 2;
            float v0 = acc[i][j][0] * alpha;
            float v1 = acc[i][j][1] * alpha;
            float v2 = acc[i][j][2] * alpha;
            float v3 = acc[i][j][3] * alpha;
            if (epi == 1) {
                v0 = fmaxf(v0, 0.0f); v1 = fmaxf(v1, 0.0f);
                v2 = fmaxf(v2, 0.0f); v3 = fmaxf(v3, 0.0f);
            } else if (epi == 2) {
                v0 += R[(long)r0 * ldc + col];
                v1 += R[(long)r0 * ldc + col + 1];
                v2 += R[(long)(r0 + 8) * ldc + col];
                v3 += R[(long)(r0 + 8) * ldc + col + 1];
            }
            if (ROUT) {
                v0 = frnd(v0); v1 = frnd(v1); v2 = frnd(v2); v3 = frnd(v3);
            }
            float2 p01; p01.x = v0; p01.y = v1;
            float2 p23; p23.x = v2; p23.y = v3;
            *reinterpret_cast<float2*>(&C[(long)r0 * ldc + col]) = p01;
            *reinterpret_cast<float2*>(&C[(long)(r0 + 8) * ldc + col]) = p23;
        }
    }
}

template <int BM, int BN, bool TB, int STAGES, bool CVTA, bool ROUT>
__global__ void __launch_bounds__(256, 2)
gemm_cp(const float* __restrict__ A, int lda, long sAb, long sAh,
        const float* __restrict__ Bg, int ldb, long sBb, long sBh,
        float* __restrict__ C, int ldc, long sCb, long sCh,
        const float* __restrict__ R,
        int K, float alpha, int epi, int hdiv) {
    extern __shared__ float smem[];
    const int z = blockIdx.z;
    const int zb = z / hdiv;
    const int zh = z % hdiv;
    gemm_body<BM, BN, TB, STAGES, CVTA, ROUT>(
        smem,
        A + (long)zb * sAb + (long)zh * sAh, lda,
        Bg + (long)zb * sBb + (long)zh * sBh, ldb,
        C + (long)zb * sCb + (long)zh * sCh, ldc,
        R, K, alpha, epi);
}

// Fused Q/K/V projection: blockIdx.z selects the weight/output pair.
__global__ void __launch_bounds__(256, 2)
qkv_cp(const float* __restrict__ x,
       const float* __restrict__ Wq, const float* __restrict__ Wk,
       const float* __restrict__ Wv,
       float* __restrict__ q, float* __restrict__ k, float* __restrict__ v) {
    extern __shared__ float smem[];
    const int z = blockIdx.z;
    const float* W = (z == 0) ? Wq : (z == 1) ? Wk : Wv;
    float* C = (z == 0) ? q : (z == 1) ? k : v;
    gemm_body<128, 128, false, 4, false, true>(smem, x, D_, W, D_, C, D_,
                                               nullptr, D_, 1.0f, 0);
}

// ---------------------------------------------------------------------------
// In-place row softmax; 128 threads, float4 per thread, shuffle reductions.
// ---------------------------------------------------------------------------
__global__ void __launch_bounds__(128)
softmax_kernel(float* __restrict__ attn, const int* __restrict__ mask) {
    const int row = blockIdx.x;
    const int b = row >> 12;
    const int t = threadIdx.x;
    float4* p = reinterpret_cast<float4*>(attn + (long)row * S_);
    const int4* mp = reinterpret_cast<const int4*>(mask + b * S_);

    float4 v = p[t];
    int4 mm = mp[t];
    if (mm.x == 0) v.x = -1e9f;
    if (mm.y == 0) v.y = -1e9f;
    if (mm.z == 0) v.z = -1e9f;
    if (mm.w == 0) v.w = -1e9f;

    float mx = fmaxf(fmaxf(v.x, v.y), fmaxf(v.z, v.w));
#pragma unroll
    for (int o = 16; o; o >>= 1) mx = fmaxf(mx, __shfl_xor_sync(0xffffffffu, mx, o));
    __shared__ float sm[4], ss[4];
    if ((t & 31) == 0) sm[t >> 5] = mx;
    __syncthreads();
    mx = fmaxf(fmaxf(sm[0], sm[1]), fmaxf(sm[2], sm[3]));

    float4 e;
    e.x = expf(v.x - mx);
    e.y = expf(v.y - mx);
    e.z = expf(v.z - mx);
    e.w = expf(v.w - mx);
    float s = e.x + e.y + e.z + e.w;
#pragma unroll
    for (int o = 16; o; o >>= 1) s += __shfl_xor_sync(0xffffffffu, s, o);
    if ((t & 31) == 0) ss[t >> 5] = s;
    __syncthreads();
    s = ss[0] + ss[1] + ss[2] + ss[3];
    const float inv = 1.0f / s;
    e.x *= inv; e.y *= inv; e.z *= inv; e.w *= inv;
    p[t] = e;
}

// ---------------------------------------------------------------------------
// LayerNorm over last dim (512); dual output (fp32 + tf32-rounded)
// ---------------------------------------------------------------------------
__global__ void ln_kernel(const float* __restrict__ in,
                          const float* __restrict__ g,
                          const float* __restrict__ bb,
                          float* __restrict__ out,
                          float* __restrict__ outr) {
    const int row = blockIdx.x;
    const float* p = in + (long)row * D_;
    const int t = threadIdx.x;

    float x0 = p[t];
    float x1 = p[t + 256];

    __shared__ float red[256];
    red[t] = x0 + x1;
    __syncthreads();
#pragma unroll
    for (int s = 128; s > 0; s >>= 1) {
        if (t < s) red[t] += red[t + s];
        __syncthreads();
    }
    const float mean = red[0] * (1.0f / D_);
    __syncthreads();

    float d0 = x0 - mean;
    float d1 = x1 - mean;
    red[t] = d0 * d0 + d1 * d1;
    __syncthreads();
#pragma unroll
    for (int s = 128; s > 0; s >>= 1) {
        if (t < s) red[t] += red[t + s];
        __syncthreads();
    }
    const float var = red[0] * (1.0f / D_);
    const float rs = rsqrtf(var + 1e-5f);

    float o0 = d0 * rs * g[t] + bb[t];
    float o1 = d1 * rs * g[t + 256] + bb[t + 256];
    float* o = out + (long)row * D_;
    o[t] = o0;
    o[t + 256] = o1;
    float* orr = outr + (long)row * D_;
    orr[t] = frnd(o0);
    orr[t + 256] = frnd(o1);
}

// ---------------------------------------------------------------------------
extern "C" void kernel_launch(void* const* d_in, const int* in_sizes, int n_in,
                              void* d_out, int out_size) {
    const float* enc = (const float*)d_in[0];
    const int* mask = (const int*)d_in[1];
    const float* Wq = (const float*)d_in[2];
    const float* Wk = (const float*)d_in[3];
    const float* Wv = (const float*)d_in[4];
    const float* Wo = (const float*)d_in[5];
    const float* ln1g = (const float*)d_in[6];
    const float* ln1b = (const float*)d_in[7];
    const float* W1 = (const float*)d_in[8];
    const float* W2 = (const float*)d_in[9];
    const float* ln2g = (const float*)d_in[10];
    const float* ln2b = (const float*)d_in[11];

    float *x, *xr, *q, *k, *v, *ctx, *tmp, *h1, *pos, *wr;
    cudaGetSymbolAddress((void**)&x, g_x);
    cudaGetSymbolAddress((void**)&xr, g_xr);
    cudaGetSymbolAddress((void**)&q, g_q);
    cudaGetSymbolAddress((void**)&k, g_k);
    cudaGetSymbolAddress((void**)&v, g_v);
    cudaGetSymbolAddress((void**)&ctx, g_ctx);
    cudaGetSymbolAddress((void**)&tmp, g_tmp);
    cudaGetSymbolAddress((void**)&h1, g_h1);
    cudaGetSymbolAddress((void**)&pos, g_pos);
    cudaGetSymbolAddress((void**)&wr, g_wr);

    // Rounded-weight scratch layout
    float* Wq_r = wr;
    float* Wk_r = Wq_r + 6 * WLD;
    float* Wv_r = Wk_r + 6 * WLD;
    float* Wo_r = Wv_r + 6 * WLD;
    float* W1_r = Wo_r + 6 * WLD;
    float* W2_r = W1_r + 6 * WF;

    float* out_x = (float*)d_out;
    float* out_attn = out_x + X_ELEMS;

    // Dynamic smem opt-in (idempotent; host-side attribute, not captured)
    constexpr int SM_PROJ = GCfg<128, 128, false, 4>::SMEM_BYTES;  // 75776
    constexpr int SM_SCOR = GCfg<128, 128, true, 4>::SMEM_BYTES;   // 81920
    constexpr int SM_CTX  = GCfg<128, 64, false, 4>::SMEM_BYTES;   // 59392
    cudaFuncSetAttribute(gemm_cp<128, 128, false, 4, false, false>,
                         cudaFuncAttributeMaxDynamicSharedMemorySize, SM_PROJ);
    cudaFuncSetAttribute(gemm_cp<128, 128, false, 4, false, true>,
                         cudaFuncAttributeMaxDynamicSharedMemorySize, SM_PROJ);
    cudaFuncSetAttribute(gemm_cp<128, 128, true, 4, false, false>,
                         cudaFuncAttributeMaxDynamicSharedMemorySize, SM_SCOR);
    cudaFuncSetAttribute(gemm_cp<128, 64, false, 4, true, true>,
                         cudaFuncAttributeMaxDynamicSharedMemorySize, SM_CTX);
    cudaFuncSetAttribute(qkv_cp,
                         cudaFuncAttributeMaxDynamicSharedMemorySize, SM_PROJ);

    // Round all weights to tf32 once per launch
    round_kernel<<<(6 * WLD / 4 + 255) / 256, 256>>>(
        (const float4*)Wq, (float4*)Wq_r, 6 * WLD / 4);
    round_kernel<<<(6 * WLD / 4 + 255) / 256, 256>>>(
        (const float4*)Wk, (float4*)Wk_r, 6 * WLD / 4);
    round_kernel<<<(6 * WLD / 4 + 255) / 256, 256>>>(
        (const float4*)Wv, (float4*)Wv_r, 6 * WLD / 4);
    round_kernel<<<(6 * WLD / 4 + 255) / 256, 256>>>(
        (const float4*)Wo, (float4*)Wo_r, 6 * WLD / 4);
    round_kernel<<<(6 * WF / 4 + 255) / 256, 256>>>(
        (const float4*)W1, (float4*)W1_r, 6 * WF / 4);
    round_kernel<<<(6 * WF / 4 + 255) / 256, 256>>>(
        (const float4*)W2, (float4*)W2_r, 6 * WF / 4);

    pos_kernel<<<(S_ * D_ + 255) / 256, 256>>>(pos);
    add_pos_kernel<<<(X_ELEMS + 255) / 256, 256>>>(x, xr, enc, pos);

    for (int l = 0; l < L_; l++) {
        float* attn_l = out_attn + (long)l * ATTN_PER_LAYER;

        // Fused Q,K,V projections: [4096,512] @ [512,512] x3 (rounded outputs)
        qkv_cp<<<dim3(4, 32, 3), 256, SM_PROJ>>>(
            xr, Wq_r + l * WLD, Wk_r + l * WLD, Wv_r + l * WLD, q, k, v);

        // Scores: per (b,h): Q[512,64] @ K^T * (1/8) -> attn region (exact fp32 out)
        gemm_cp<128, 128, true, 4, false, false><<<dim3(4, 4, B_ * H_), 256, SM_SCOR>>>(
            q, D_, (long)S_ * D_, DK_,
            k, D_, (long)S_ * D_, DK_,
            attn_l, S_, (long)H_ * S_ * S_, (long)S_ * S_,
            nullptr, DK_, 0.125f, 0, H_);

        // Softmax (in place, applies pad mask)
        softmax_kernel<<<B_ * H_ * S_, 128>>>(attn_l, mask);

        // ctx: per (b,h): attn[512,512] @ V[512,64] (A needs cvt; rounded out)
        gemm_cp<128, 64, false, 4, true, true><<<dim3(1, 4, B_ * H_), 256, SM_CTX>>>(
            attn_l, S_, (long)H_ * S_ * S_, (long)S_ * S_,
            v, D_, (long)S_ * D_, DV_,
            ctx, D_, (long)S_ * D_, DV_,
            nullptr, S_, 1.0f, 0, H_);

        // Wo projection + residual(x fp32), then LN1 -> (x, xr)
        gemm_cp<128, 128, false, 4, false, false><<<dim3(4, 32, 1), 256, SM_PROJ>>>(
            ctx, D_, 0, 0, Wo_r + l * WLD, D_, 0, 0, tmp, D_, 0, 0, x, D_,
            1.0f, 2, 1);
        ln_kernel<<<M_, 256>>>(tmp, ln1g + l * D_, ln1b + l * D_, x, xr);

        // FFN: relu(xr @ W1) (rounded) @ W2 + x, then LN2 -> (x, xr)
        gemm_cp<128, 128, false, 4, false, true><<<dim3(16, 32, 1), 256, SM_PROJ>>>(
            xr, D_, 0, 0, W1_r + l * WF, DFF_, 0, 0, h1, DFF_, 0, 0, nullptr, D_,
            1.0f, 1, 1);
        gemm_cp<128, 128, false, 4, false, false><<<dim3(4, 32, 1), 256, SM_PROJ>>>(
            h1, DFF_, 0, 0, W2_r + l * WF, D_, 0, 0, tmp, D_, 0, 0, x, DFF_,
            1.0f, 2, 1);
        ln_kernel<<<M_, 256>>>(tmp, ln2g + l * D_, ln2b + l * D_, x, xr);
    }

    cudaMemcpyAsync(out_x, x, (size_t)X_ELEMS * sizeof(float),
                    cudaMemcpyDeviceToDevice, 0);
}